// round 3
// baseline (speedup 1.0000x reference)
#include <cuda_runtime.h>
#include <cuda_bf16.h>
#include <cstdint>

// Problem constants (shapes fixed by the dataset)
#define D_DIM   128
#define K_DIM   512
#define N_MAX   262144

#define DECAY_F 0.99f
#define ONE_M_DECAY 0.01f
#define EPS_F   1e-5f
#define COMMIT  0.25f

#define SM_STRIDE 132   // 128 + 4 pad (keeps float4 alignment, breaks bank aliasing)

// -------- device scratch (static: no allocation) --------
__device__ int   g_indices[N_MAX];
__device__ float g_counts[K_DIM];
__device__ float g_dw[K_DIM * D_DIM];
__device__ float g_enorm[K_DIM];
__device__ float g_loss_part[64];

// ============================================================
// Kernel 1: zero accumulators + compute ||e_k||^2
// grid: 64 blocks x 256 threads = 16384 threads = 512 warps (1 warp per k-row)
// ============================================================
__global__ void __launch_bounds__(256) init_kernel(const float* __restrict__ emb) {
    int tid  = blockIdx.x * blockDim.x + threadIdx.x;

    for (int i = tid; i < K_DIM * D_DIM; i += 16384) g_dw[i] = 0.0f;
    if (tid < K_DIM) g_counts[tid] = 0.0f;
    if (tid < 64)    g_loss_part[tid] = 0.0f;

    int w    = tid >> 5;     // 0..511 = k row
    int lane = tid & 31;
    float4 v = *reinterpret_cast<const float4*>(&emb[w * D_DIM + lane * 4]);
    float s = v.x * v.x + v.y * v.y + v.z * v.z + v.w * v.w;
    #pragma unroll
    for (int off = 16; off > 0; off >>= 1)
        s += __shfl_xor_sync(0xFFFFFFFFu, s, off);
    if (lane == 0) g_enorm[w] = s;
}

// ============================================================
// Kernel 2: fused fp32 GEMM + argmin.
// score[n][k] = ||e_k||^2 - 2 * dot(z_n, e_k)  (||z||^2 dropped: row-constant)
// CTA: 128 z-rows x all 512 k in 4 tiles of 128. 256 threads, 8x8 micro-tile.
// Tiles stored d-major in smem: zs[d][r], es[d][c], stride 132.
// ============================================================
__global__ void __launch_bounds__(256, 1)
argmin_kernel(const float* __restrict__ z, const float* __restrict__ emb,
              float* __restrict__ idxf_out) {
    extern __shared__ float smem[];
    float* zs = smem;                          // [128][132]
    float* es = smem + D_DIM * SM_STRIDE;      // [128][132]
    float* en = smem + 2 * D_DIM * SM_STRIDE;  // [128]

    const int tid = threadIdx.x;
    const int m0  = blockIdx.x * 128;

    // load z tile, transposed to d-major (coalesced global reads)
    for (int t = tid; t < 128 * D_DIM; t += 256) {
        int r = t >> 7, d = t & 127;
        zs[d * SM_STRIDE + r] = z[(m0 + r) * D_DIM + d];
    }

    const int ty = tid >> 4, tx = tid & 15;
    const int r0 = ty * 8,   c0 = tx * 8;

    float best[8];
    int   besti[8];
    #pragma unroll
    for (int i = 0; i < 8; i++) { best[i] = 3.4e38f; besti[i] = 0; }

    for (int kt = 0; kt < K_DIM / 128; kt++) {
        __syncthreads();
        for (int t = tid; t < 128 * D_DIM; t += 256) {
            int r = t >> 7, d = t & 127;
            es[d * SM_STRIDE + r] = emb[(kt * 128 + r) * D_DIM + d];
        }
        if (tid < 128) en[tid] = g_enorm[kt * 128 + tid];
        __syncthreads();

        float acc[8][8];
        #pragma unroll
        for (int i = 0; i < 8; i++)
            #pragma unroll
            for (int j = 0; j < 8; j++) acc[i][j] = 0.0f;

        const float* zp = zs + r0;
        const float* ep = es + c0;
        #pragma unroll 4
        for (int d = 0; d < D_DIM; d++) {
            float4 a0 = *reinterpret_cast<const float4*>(zp + d * SM_STRIDE);
            float4 a1 = *reinterpret_cast<const float4*>(zp + d * SM_STRIDE + 4);
            float4 b0 = *reinterpret_cast<const float4*>(ep + d * SM_STRIDE);
            float4 b1 = *reinterpret_cast<const float4*>(ep + d * SM_STRIDE + 4);
            float a[8] = {a0.x, a0.y, a0.z, a0.w, a1.x, a1.y, a1.z, a1.w};
            float b[8] = {b0.x, b0.y, b0.z, b0.w, b1.x, b1.y, b1.z, b1.w};
            #pragma unroll
            for (int i = 0; i < 8; i++)
                #pragma unroll
                for (int j = 0; j < 8; j++)
                    acc[i][j] += a[i] * b[j];
        }

        // epilogue: running argmin (ascending j keeps lowest index on ties)
        #pragma unroll
        for (int j = 0; j < 8; j++) {
            float enj = en[c0 + j];
            int   c   = kt * 128 + c0 + j;
            #pragma unroll
            for (int i = 0; i < 8; i++) {
                float s = enj - 2.0f * acc[i][j];
                if (s < best[i]) { best[i] = s; besti[i] = c; }
            }
        }
    }

    // cross-thread reduce over the 16 tx-slices of each row (reuse es as scratch)
    __syncthreads();
    float* redv = es;                               // [128][16]
    int*   redi = reinterpret_cast<int*>(es + 128 * 16);
    #pragma unroll
    for (int i = 0; i < 8; i++) {
        redv[(r0 + i) * 16 + tx] = best[i];
        redi[(r0 + i) * 16 + tx] = besti[i];
    }
    __syncthreads();
    if (tid < 128) {
        int r = tid;
        float bv = redv[r * 16];
        int   bi = redi[r * 16];
        #pragma unroll
        for (int t = 1; t < 16; t++) {
            float v = redv[r * 16 + t];
            int  ii = redi[r * 16 + t];
            if (v < bv || (v == bv && ii < bi)) { bv = v; bi = ii; }
        }
        g_indices[m0 + r] = bi;
        idxf_out[m0 + r]  = (float)bi;
    }
}

// ============================================================
// Kernel 3: gather z_q, write straight-through output, loss partials,
// counts + dw segment sums. 1 warp per z-row, 8 rows per block.
// ============================================================
__global__ void __launch_bounds__(256)
scatter_kernel(const float* __restrict__ z, const float* __restrict__ emb,
               float* __restrict__ zq_out) {
    const int warp = threadIdx.x >> 5;          // 0..7
    const int lane = threadIdx.x & 31;
    const int row  = blockIdx.x * 8 + warp;

    const int idx = g_indices[row];

    float4 f = *reinterpret_cast<const float4*>(&z[row * D_DIM + lane * 4]);
    float4 q = *reinterpret_cast<const float4*>(&emb[idx * D_DIM + lane * 4]);

    float dx = q.x - f.x, dy = q.y - f.y, dz = q.z - f.z, dw4 = q.w - f.w;
    float4 st = make_float4(f.x + dx, f.y + dy, f.z + dz, f.w + dw4);
    *reinterpret_cast<float4*>(&zq_out[row * D_DIM + lane * 4]) = st;

    float lsum = dx * dx + dy * dy + dz * dz + dw4 * dw4;

    // dw segment-sum (scalar fp32 reductions; lanes cover a contiguous 512B span)
    float* dwp = &g_dw[idx * D_DIM + lane * 4];
    atomicAdd(dwp + 0, f.x);
    atomicAdd(dwp + 1, f.y);
    atomicAdd(dwp + 2, f.z);
    atomicAdd(dwp + 3, f.w);

    if (lane == 0) atomicAdd(&g_counts[idx], 1.0f);

    // block-level loss reduce -> 64-way partials
    #pragma unroll
    for (int off = 16; off > 0; off >>= 1)
        lsum += __shfl_xor_sync(0xFFFFFFFFu, lsum, off);
    __shared__ float s_l[8];
    if (lane == 0) s_l[warp] = lsum;
    __syncthreads();
    if (threadIdx.x == 0) {
        float b = 0.0f;
        #pragma unroll
        for (int w = 0; w < 8; w++) b += s_l[w];
        atomicAdd(&g_loss_part[blockIdx.x & 63], b);
    }
}

// ============================================================
// Kernel 4: finalize — EMA updates, cluster-size smoothing, new embedding, loss.
// Single block, 512 threads (one per k).
// ============================================================
__global__ void __launch_bounds__(512)
finalize_kernel(const float* __restrict__ ecs, const float* __restrict__ emaw,
                float* __restrict__ o_ecs, float* __restrict__ o_emaw,
                float* __restrict__ o_emb, float* __restrict__ o_loss, int N) {
    const int k = threadIdx.x;
    __shared__ float red[K_DIM];
    __shared__ float s_cs[K_DIM];

    float necs = ecs[k] * DECAY_F + ONE_M_DECAY * g_counts[k];
    o_ecs[k] = necs;
    red[k] = necs;
    __syncthreads();
    #pragma unroll
    for (int s = 256; s > 0; s >>= 1) {
        if (k < s) red[k] += red[k + s];
        __syncthreads();
    }
    float n = red[0];
    s_cs[k] = (necs + EPS_F) / (n + (float)K_DIM * EPS_F) * n;
    __syncthreads();

    for (int i = k; i < K_DIM * D_DIM; i += K_DIM) {
        int kk = i >> 7;
        float w = emaw[i] * DECAY_F + ONE_M_DECAY * g_dw[i];
        o_emaw[i] = w;
        o_emb[i]  = w / s_cs[kk];
    }

    if (k == 0) {
        float L = 0.0f;
        #pragma unroll
        for (int j = 0; j < 64; j++) L += g_loss_part[j];
        *o_loss = COMMIT * L / ((float)N * (float)D_DIM);
    }
}

// ============================================================
// launch
// ============================================================
extern "C" void kernel_launch(void* const* d_in, const int* in_sizes, int n_in,
                              void* d_out, int out_size) {
    const float* z    = (const float*)d_in[0];   // [N, 128]
    const float* emb  = (const float*)d_in[1];   // [512, 128]
    const float* ecs  = (const float*)d_in[2];   // [512]
    const float* emaw = (const float*)d_in[3];   // [512, 128]

    const int ND = in_sizes[0];
    const int KD = in_sizes[1];
    const int K  = in_sizes[2];
    const int N  = ND / D_DIM;

    float* out    = (float*)d_out;
    float* o_zq   = out;                 // N*D
    float* o_loss = o_zq + ND;           // 1
    float* o_idx  = o_loss + 1;          // N
    float* o_ecs  = o_idx + N;           // K
    float* o_emaw = o_ecs + K;           // K*D
    float* o_emb  = o_emaw + KD;         // K*D

    const size_t smem_bytes = (size_t)(2 * D_DIM * SM_STRIDE + 128) * sizeof(float);
    cudaFuncSetAttribute(argmin_kernel,
                         cudaFuncAttributeMaxDynamicSharedMemorySize,
                         (int)smem_bytes);

    init_kernel<<<64, 256>>>(emb);
    argmin_kernel<<<N / 128, 256, smem_bytes>>>(z, emb, o_idx);
    scatter_kernel<<<N / 8, 256>>>(z, emb, o_zq);
    finalize_kernel<<<1, 512>>>(ecs, emaw, o_ecs, o_emaw, o_emb, o_loss, N);
}

// round 6
// speedup vs baseline: 1.1754x; 1.1754x over previous
#include <cuda_runtime.h>
#include <cuda_bf16.h>
#include <cstdint>

#define D_DIM   128
#define K_DIM   512
#define N_MAX   262144

#define DECAY_F 0.99f
#define ONE_M_DECAY 0.01f
#define EPS_F   1e-5f
#define COMMIT  0.25f

#define ZSTRIDE 132   // padded row stride (floats) for z tiles
#define ESTRIDE 132   // padded row stride for e chunk

// -------- device scratch (static: no allocation) --------
__device__ int   g_indices[N_MAX];
__device__ float g_counts[K_DIM];
__device__ float g_dw[K_DIM * D_DIM];
__device__ float g_enorm[K_DIM];
__device__ float g_loss_part[64];
__device__ float g_cs[K_DIM];

__device__ __forceinline__ float tf32_rna(float x) {
    float r; asm("cvt.rna.tf32.f32 %0, %1;" : "=f"(r) : "f"(x)); return r;
}

// D += A(16x8 tf32, row) * B(8x8 tf32, col)   [base-PTX, sm_80+]
__device__ __forceinline__ void mma_tf32(float* d, const uint32_t* a, const uint32_t* b) {
    asm volatile(
        "mma.sync.aligned.m16n8k8.row.col.f32.tf32.tf32.f32 "
        "{%0,%1,%2,%3}, {%4,%5,%6,%7}, {%8,%9}, {%0,%1,%2,%3};"
        : "+f"(d[0]), "+f"(d[1]), "+f"(d[2]), "+f"(d[3])
        : "r"(a[0]), "r"(a[1]), "r"(a[2]), "r"(a[3]), "r"(b[0]), "r"(b[1]));
}

// ============================================================
// Kernel 1: zero accumulators + ||e_k||^2
// ============================================================
__global__ void __launch_bounds__(256) init_kernel(const float* __restrict__ emb) {
    int tid = blockIdx.x * blockDim.x + threadIdx.x;
    for (int i = tid; i < K_DIM * D_DIM; i += 16384) g_dw[i] = 0.0f;
    if (tid < K_DIM) g_counts[tid] = 0.0f;
    if (tid < 64)    g_loss_part[tid] = 0.0f;

    int w = tid >> 5, lane = tid & 31;
    float4 v = *reinterpret_cast<const float4*>(&emb[w * D_DIM + lane * 4]);
    float s = v.x * v.x + v.y * v.y + v.z * v.z + v.w * v.w;
    #pragma unroll
    for (int off = 16; off > 0; off >>= 1) s += __shfl_xor_sync(0xFFFFFFFFu, s, off);
    if (lane == 0) g_enorm[w] = s;
}

// ============================================================
// Kernel 2: 3xTF32 mma.sync GEMM + fused argmin.
// CTA: 128 z-rows x 512 codes. 256 threads = 8 warps as 4(m) x 2(n).
// z hi/lo persist in smem; e processed in 8 chunks of 64 codes (hi/lo).
// score[n][k] = ||e_k||^2 - 2 * dot(z_n, e_k); per-thread running argmin.
// ============================================================
__global__ void __launch_bounds__(256, 1)
argmin_kernel(const float* __restrict__ z, const float* __restrict__ emb,
              float* __restrict__ idxf_out) {
    extern __shared__ float sm[];
    float* zh = sm;                              // [128][132]
    float* zl = zh + 128 * ZSTRIDE;              // [128][132]
    float* eh = zl + 128 * ZSTRIDE;              // [64][132]
    float* el = eh + 64 * ESTRIDE;               // [64][132]
    __shared__ float en[K_DIM];

    const int tid  = threadIdx.x;
    const int warp = tid >> 5;
    const int lane = tid & 31;
    const int g    = lane >> 2;      // groupID (0..7)
    const int tig  = lane & 3;       // threadID_in_group (0..3)
    const int wm   = warp >> 1;      // 0..3  (rows wm*32 .. +32)
    const int wn   = warp & 1;       // 0..1  (cols wn*32 within chunk)
    const int m0   = blockIdx.x * 128;

    #pragma unroll
    for (int i = 0; i < 2; i++) en[tid + i * 256] = g_enorm[tid + i * 256];

    // ---- split z tile into tf32 hi/lo (coalesced loads) ----
    for (int idx = tid; idx < 128 * D_DIM; idx += 256) {
        int r = idx >> 7, d = idx & 127;
        float v  = z[(size_t)(m0 + r) * D_DIM + d];
        float hh = tf32_rna(v);
        float ll = tf32_rna(v - hh);
        zh[r * ZSTRIDE + d] = hh;
        zl[r * ZSTRIDE + d] = ll;
    }

    // best[ri]: ri = (mf<<1) | half, covering rows wm*32 + mf*16 + half*8 + g
    float best[4];
    int   besti[4];
    #pragma unroll
    for (int i = 0; i < 4; i++) { best[i] = 3.4e38f; besti[i] = 0; }

    const int rbase = wm * 32 + g;

    for (int ch = 0; ch < 8; ch++) {
        __syncthreads();   // previous chunk's MMAs done reading eh/el
        for (int idx = tid; idx < 64 * D_DIM; idx += 256) {
            int n = idx >> 7, d = idx & 127;
            float v  = emb[(size_t)(ch * 64 + n) * D_DIM + d];
            float hh = tf32_rna(v);
            float ll = tf32_rna(v - hh);
            eh[n * ESTRIDE + d] = hh;
            el[n * ESTRIDE + d] = ll;
        }
        __syncthreads();

        float acc[2][4][4];
        #pragma unroll
        for (int mf = 0; mf < 2; mf++)
            #pragma unroll
            for (int nf = 0; nf < 4; nf++)
                #pragma unroll
                for (int c = 0; c < 4; c++) acc[mf][nf][c] = 0.0f;

        #pragma unroll 2
        for (int ks = 0; ks < 16; ks++) {
            const int k0 = ks * 8;

            // A fragments (m16k8): a0=(g,tig) a1=(g+8,tig) a2=(g,tig+4) a3=(g+8,tig+4)
            uint32_t ah[2][4], al[2][4];
            #pragma unroll
            for (int mf = 0; mf < 2; mf++) {
                const int base = (rbase + mf * 16) * ZSTRIDE + k0 + tig;
                ah[mf][0] = __float_as_uint(zh[base]);
                ah[mf][1] = __float_as_uint(zh[base + 8 * ZSTRIDE]);
                ah[mf][2] = __float_as_uint(zh[base + 4]);
                ah[mf][3] = __float_as_uint(zh[base + 8 * ZSTRIDE + 4]);
                al[mf][0] = __float_as_uint(zl[base]);
                al[mf][1] = __float_as_uint(zl[base + 8 * ZSTRIDE]);
                al[mf][2] = __float_as_uint(zl[base + 4]);
                al[mf][3] = __float_as_uint(zl[base + 8 * ZSTRIDE + 4]);
            }
            // B fragments (k8n8, col-major): b0=(k=tig, n=g) b1=(k=tig+4, n=g)
            uint32_t bh[4][2], bl[4][2];
            #pragma unroll
            for (int nf = 0; nf < 4; nf++) {
                const int nb   = wn * 32 + nf * 8 + g;
                const int base = nb * ESTRIDE + k0 + tig;
                bh[nf][0] = __float_as_uint(eh[base]);
                bh[nf][1] = __float_as_uint(eh[base + 4]);
                bl[nf][0] = __float_as_uint(el[base]);
                bl[nf][1] = __float_as_uint(el[base + 4]);
            }

            // term 1: hi*hi  (8 independent accumulators between dependent reuses)
            #pragma unroll
            for (int mf = 0; mf < 2; mf++)
                #pragma unroll
                for (int nf = 0; nf < 4; nf++) mma_tf32(acc[mf][nf], ah[mf], bh[nf]);
            // term 2: hi*lo
            #pragma unroll
            for (int mf = 0; mf < 2; mf++)
                #pragma unroll
                for (int nf = 0; nf < 4; nf++) mma_tf32(acc[mf][nf], ah[mf], bl[nf]);
            // term 3: lo*hi
            #pragma unroll
            for (int mf = 0; mf < 2; mf++)
                #pragma unroll
                for (int nf = 0; nf < 4; nf++) mma_tf32(acc[mf][nf], al[mf], bh[nf]);
        }

        // epilogue. Accumulator c holds (row = base + (c>>1)*8, col = colb + (c&1)).
        // Column traversal is ascending -> lowest-index tie-break preserved.
        #pragma unroll
        for (int mf = 0; mf < 2; mf++) {
            #pragma unroll
            for (int nf = 0; nf < 4; nf++) {
                const int colb = ch * 64 + wn * 32 + nf * 8 + 2 * tig;
                #pragma unroll
                for (int c = 0; c < 4; c++) {
                    const int col = colb + (c & 1);
                    const int ri  = mf * 2 + (c >> 1);
                    float s = en[col] - 2.0f * acc[mf][nf][c];
                    if (s < best[ri]) { best[ri] = s; besti[ri] = col; }
                }
            }
        }
    }

    // ---- final per-row reduce (8 contributors/row), reuse eh region ----
    __syncthreads();
    float* redv = eh;                                   // [128][8]
    int*   redi = reinterpret_cast<int*>(eh + 128 * 8); // [128][8]
    const int slot = tig * 2 + wn;
    #pragma unroll
    for (int ri = 0; ri < 4; ri++) {
        const int r = wm * 32 + (ri >> 1) * 16 + (ri & 1) * 8 + g;
        redv[r * 8 + slot] = best[ri];
        redi[r * 8 + slot] = besti[ri];
    }
    __syncthreads();
    if (tid < 128) {
        float bv = redv[tid * 8];
        int   bi = redi[tid * 8];
        #pragma unroll
        for (int t = 1; t < 8; t++) {
            float v = redv[tid * 8 + t];
            int  ii = redi[tid * 8 + t];
            if (v < bv || (v == bv && ii < bi)) { bv = v; bi = ii; }
        }
        g_indices[m0 + tid] = bi;
        idxf_out[m0 + tid]  = (float)bi;
    }
}

// ============================================================
// Kernel 3: gather z_q, straight-through output, loss partials,
// counts + dw segment sums. 1 warp per z-row, 8 rows per block.
// ============================================================
__global__ void __launch_bounds__(256)
scatter_kernel(const float* __restrict__ z, const float* __restrict__ emb,
               float* __restrict__ zq_out) {
    const int warp = threadIdx.x >> 5;
    const int lane = threadIdx.x & 31;
    const int row  = blockIdx.x * 8 + warp;

    const int idx = g_indices[row];

    float4 f = *reinterpret_cast<const float4*>(&z[(size_t)row * D_DIM + lane * 4]);
    float4 q = *reinterpret_cast<const float4*>(&emb[(size_t)idx * D_DIM + lane * 4]);

    float dx = q.x - f.x, dy = q.y - f.y, dz = q.z - f.z, dw4 = q.w - f.w;
    float4 st = make_float4(f.x + dx, f.y + dy, f.z + dz, f.w + dw4);
    *reinterpret_cast<float4*>(&zq_out[(size_t)row * D_DIM + lane * 4]) = st;

    float lsum = dx * dx + dy * dy + dz * dz + dw4 * dw4;

    float* dwp = &g_dw[idx * D_DIM + lane * 4];
    atomicAdd(dwp + 0, f.x);
    atomicAdd(dwp + 1, f.y);
    atomicAdd(dwp + 2, f.z);
    atomicAdd(dwp + 3, f.w);

    if (lane == 0) atomicAdd(&g_counts[idx], 1.0f);

    #pragma unroll
    for (int off = 16; off > 0; off >>= 1) lsum += __shfl_xor_sync(0xFFFFFFFFu, lsum, off);
    __shared__ float s_l[8];
    if (lane == 0) s_l[warp] = lsum;
    __syncthreads();
    if (threadIdx.x == 0) {
        float b = 0.0f;
        #pragma unroll
        for (int w = 0; w < 8; w++) b += s_l[w];
        atomicAdd(&g_loss_part[blockIdx.x & 63], b);
    }
}

// ============================================================
// Kernel 4a: scalar finalize — ecs EMA, n-reduce, cluster size, loss.
// ============================================================
__global__ void __launch_bounds__(512)
finalize_a(const float* __restrict__ ecs, float* __restrict__ o_ecs,
           float* __restrict__ o_loss, int N) {
    const int k = threadIdx.x;
    __shared__ float red[K_DIM];

    float necs = ecs[k] * DECAY_F + ONE_M_DECAY * g_counts[k];
    o_ecs[k] = necs;
    red[k] = necs;
    __syncthreads();
    #pragma unroll
    for (int s = 256; s > 0; s >>= 1) {
        if (k < s) red[k] += red[k + s];
        __syncthreads();
    }
    float n = red[0];
    g_cs[k] = (necs + EPS_F) / (n + (float)K_DIM * EPS_F) * n;

    if (k == 0) {
        float L = 0.0f;
        #pragma unroll
        for (int j = 0; j < 64; j++) L += g_loss_part[j];
        *o_loss = COMMIT * L / ((float)N * (float)D_DIM);
    }
}

// ============================================================
// Kernel 4b: wide finalize — ema_w EMA + new embedding (K*D elems).
// ============================================================
__global__ void __launch_bounds__(256)
finalize_b(const float* __restrict__ emaw, float* __restrict__ o_emaw,
           float* __restrict__ o_emb) {
    int i = blockIdx.x * 256 + threadIdx.x;
    float w = emaw[i] * DECAY_F + ONE_M_DECAY * g_dw[i];
    o_emaw[i] = w;
    o_emb[i]  = w / g_cs[i >> 7];
}

// ============================================================
// launch
// ============================================================
extern "C" void kernel_launch(void* const* d_in, const int* in_sizes, int n_in,
                              void* d_out, int out_size) {
    const float* z    = (const float*)d_in[0];   // [N, 128]
    const float* emb  = (const float*)d_in[1];   // [512, 128]
    const float* ecs  = (const float*)d_in[2];   // [512]
    const float* emaw = (const float*)d_in[3];   // [512, 128]

    const int ND = in_sizes[0];
    const int KD = in_sizes[1];
    const int K  = in_sizes[2];
    const int N  = ND / D_DIM;

    float* out    = (float*)d_out;
    float* o_zq   = out;                 // N*D
    float* o_loss = o_zq + ND;           // 1
    float* o_idx  = o_loss + 1;          // N
    float* o_ecs  = o_idx + N;           // K
    float* o_emaw = o_ecs + K;           // K*D
    float* o_emb  = o_emaw + KD;         // K*D

    // dyn smem: zh+zl (2*128*132) + eh+el (2*64*132) floats
    const int dyn_smem = (2 * 128 * ZSTRIDE + 2 * 64 * ESTRIDE) * 4;
    cudaFuncSetAttribute(argmin_kernel,
                         cudaFuncAttributeMaxDynamicSharedMemorySize, dyn_smem);

    init_kernel<<<64, 256>>>(emb);
    argmin_kernel<<<N / 128, 256, dyn_smem>>>(z, emb, o_idx);
    scatter_kernel<<<N / 8, 256>>>(z, emb, o_zq);
    finalize_a<<<1, 512>>>(ecs, o_ecs, o_loss, N);
    finalize_b<<<KD / 256, 256>>>(emaw, o_emaw, o_emb);
}

// round 7
// speedup vs baseline: 1.5212x; 1.2942x over previous
#include <cuda_runtime.h>
#include <cuda_bf16.h>
#include <cstdint>

#define D_DIM   128
#define K_DIM   512
#define N_MAX   262144

#define DECAY_F 0.99f
#define ONE_M_DECAY 0.01f
#define EPS_F   1e-5f
#define COMMIT  0.25f

#define ZSTRIDE 132   // padded row stride (floats) for z tile
#define ESTRIDE 132   // padded row stride for e chunk

// -------- device scratch (static: no allocation) --------
__device__ int   g_indices[N_MAX];
__device__ float g_counts[K_DIM];
__device__ float g_dw[K_DIM * D_DIM];
__device__ float g_enorm[K_DIM];
__device__ float g_loss_part[64];
__device__ float g_cs[K_DIM];

// hi = tf32-truncation of v (the exact bits the tensor core keeps); lo = v - hi (exact).
__device__ __forceinline__ uint32_t tf32_hi(float v) {
    return __float_as_uint(v) & 0xFFFFE000u;
}
__device__ __forceinline__ uint32_t tf32_lo(float v, uint32_t hi) {
    return __float_as_uint(v - __uint_as_float(hi));
}

// D += A(16x8 tf32, row) * B(8x8 tf32, col)   [base-PTX, sm_80+]
__device__ __forceinline__ void mma_tf32(float* d, const uint32_t* a, const uint32_t* b) {
    asm volatile(
        "mma.sync.aligned.m16n8k8.row.col.f32.tf32.tf32.f32 "
        "{%0,%1,%2,%3}, {%4,%5,%6,%7}, {%8,%9}, {%0,%1,%2,%3};"
        : "+f"(d[0]), "+f"(d[1]), "+f"(d[2]), "+f"(d[3])
        : "r"(a[0]), "r"(a[1]), "r"(a[2]), "r"(a[3]), "r"(b[0]), "r"(b[1]));
}

// ============================================================
// Kernel 1: zero accumulators + ||e_k||^2
// ============================================================
__global__ void __launch_bounds__(256) init_kernel(const float* __restrict__ emb) {
    int tid = blockIdx.x * blockDim.x + threadIdx.x;
    for (int i = tid; i < K_DIM * D_DIM; i += 16384) g_dw[i] = 0.0f;
    if (tid < K_DIM) g_counts[tid] = 0.0f;
    if (tid < 64)    g_loss_part[tid] = 0.0f;

    int w = tid >> 5, lane = tid & 31;
    float4 v = *reinterpret_cast<const float4*>(&emb[w * D_DIM + lane * 4]);
    float s = v.x * v.x + v.y * v.y + v.z * v.z + v.w * v.w;
    #pragma unroll
    for (int off = 16; off > 0; off >>= 1) s += __shfl_xor_sync(0xFFFFFFFFu, s, off);
    if (lane == 0) g_enorm[w] = s;
}

// ============================================================
// Kernel 2: 3xTF32 mma.sync GEMM + fused argmin. fp32 tiles in smem,
// hi/lo split at fragment load (LOP+FADD). 99KB smem -> 2 CTAs/SM.
// CTA: 128 z-rows x 512 codes. 256 threads = 8 warps as 4(m) x 2(n).
// ============================================================
__global__ void __launch_bounds__(256, 2)
argmin_kernel(const float* __restrict__ z, const float* __restrict__ emb,
              float* __restrict__ idxf_out) {
    extern __shared__ float sm[];
    float* zs = sm;                              // [128][132] fp32
    float* es = zs + 128 * ZSTRIDE;              // [64][132]  fp32
    __shared__ float en[K_DIM];

    const int tid  = threadIdx.x;
    const int warp = tid >> 5;
    const int lane = tid & 31;
    const int g    = lane >> 2;      // groupID (0..7)
    const int tig  = lane & 3;       // threadID_in_group (0..3)
    const int wm   = warp >> 1;      // 0..3  (rows wm*32 .. +32)
    const int wn   = warp & 1;       // 0..1  (cols wn*32 within chunk)
    const int m0   = blockIdx.x * 128;

    #pragma unroll
    for (int i = 0; i < 2; i++) en[tid + i * 256] = g_enorm[tid + i * 256];

    // ---- stage z tile as fp32 (coalesced) ----
    for (int idx = tid; idx < 128 * D_DIM; idx += 256) {
        int r = idx >> 7, d = idx & 127;
        zs[r * ZSTRIDE + d] = z[(size_t)(m0 + r) * D_DIM + d];
    }

    // best[ri]: ri = (mf<<1) | half, covering rows wm*32 + mf*16 + half*8 + g
    float best[4];
    int   besti[4];
    #pragma unroll
    for (int i = 0; i < 4; i++) { best[i] = 3.4e38f; besti[i] = 0; }

    const int rbase = wm * 32 + g;

    for (int ch = 0; ch < 8; ch++) {
        __syncthreads();   // previous chunk's MMAs done reading es
        for (int idx = tid; idx < 64 * D_DIM; idx += 256) {
            int n = idx >> 7, d = idx & 127;
            es[n * ESTRIDE + d] = emb[(size_t)(ch * 64 + n) * D_DIM + d];
        }
        __syncthreads();

        float acc[2][4][4];
        #pragma unroll
        for (int mf = 0; mf < 2; mf++)
            #pragma unroll
            for (int nf = 0; nf < 4; nf++)
                #pragma unroll
                for (int c = 0; c < 4; c++) acc[mf][nf][c] = 0.0f;

        #pragma unroll 2
        for (int ks = 0; ks < 16; ks++) {
            const int k0 = ks * 8;

            // A fragments (m16k8): a0=(g,tig) a1=(g+8,tig) a2=(g,tig+4) a3=(g+8,tig+4)
            uint32_t ah[2][4], al[2][4];
            #pragma unroll
            for (int mf = 0; mf < 2; mf++) {
                const int base = (rbase + mf * 16) * ZSTRIDE + k0 + tig;
                float v0 = zs[base];
                float v1 = zs[base + 8 * ZSTRIDE];
                float v2 = zs[base + 4];
                float v3 = zs[base + 8 * ZSTRIDE + 4];
                ah[mf][0] = tf32_hi(v0);  al[mf][0] = tf32_lo(v0, ah[mf][0]);
                ah[mf][1] = tf32_hi(v1);  al[mf][1] = tf32_lo(v1, ah[mf][1]);
                ah[mf][2] = tf32_hi(v2);  al[mf][2] = tf32_lo(v2, ah[mf][2]);
                ah[mf][3] = tf32_hi(v3);  al[mf][3] = tf32_lo(v3, ah[mf][3]);
            }
            // B fragments (k8n8, col-major): b0=(k=tig, n=g) b1=(k=tig+4, n=g)
            uint32_t bh[4][2], bl[4][2];
            #pragma unroll
            for (int nf = 0; nf < 4; nf++) {
                const int nb   = wn * 32 + nf * 8 + g;
                const int base = nb * ESTRIDE + k0 + tig;
                float v0 = es[base];
                float v1 = es[base + 4];
                bh[nf][0] = tf32_hi(v0);  bl[nf][0] = tf32_lo(v0, bh[nf][0]);
                bh[nf][1] = tf32_hi(v1);  bl[nf][1] = tf32_lo(v1, bh[nf][1]);
            }

            // term 1: hi*hi  (8 independent accumulators between dependent reuses)
            #pragma unroll
            for (int mf = 0; mf < 2; mf++)
                #pragma unroll
                for (int nf = 0; nf < 4; nf++) mma_tf32(acc[mf][nf], ah[mf], bh[nf]);
            // term 2: hi*lo
            #pragma unroll
            for (int mf = 0; mf < 2; mf++)
                #pragma unroll
                for (int nf = 0; nf < 4; nf++) mma_tf32(acc[mf][nf], ah[mf], bl[nf]);
            // term 3: lo*hi
            #pragma unroll
            for (int mf = 0; mf < 2; mf++)
                #pragma unroll
                for (int nf = 0; nf < 4; nf++) mma_tf32(acc[mf][nf], al[mf], bh[nf]);
        }

        // epilogue. Accumulator c holds (row = base + (c>>1)*8, col = colb + (c&1)).
        // Column traversal ascending -> lowest-index tie-break preserved.
        #pragma unroll
        for (int mf = 0; mf < 2; mf++) {
            #pragma unroll
            for (int nf = 0; nf < 4; nf++) {
                const int colb = ch * 64 + wn * 32 + nf * 8 + 2 * tig;
                #pragma unroll
                for (int c = 0; c < 4; c++) {
                    const int col = colb + (c & 1);
                    const int ri  = mf * 2 + (c >> 1);
                    float s = en[col] - 2.0f * acc[mf][nf][c];
                    if (s < best[ri]) { best[ri] = s; besti[ri] = col; }
                }
            }
        }
    }

    // ---- final per-row reduce (8 contributors/row), reuse es region ----
    __syncthreads();
    float* redv = es;                                   // [128][8]
    int*   redi = reinterpret_cast<int*>(es + 128 * 8); // [128][8]
    const int slot = tig * 2 + wn;
    #pragma unroll
    for (int ri = 0; ri < 4; ri++) {
        const int r = wm * 32 + (ri >> 1) * 16 + (ri & 1) * 8 + g;
        redv[r * 8 + slot] = best[ri];
        redi[r * 8 + slot] = besti[ri];
    }
    __syncthreads();
    if (tid < 128) {
        float bv = redv[tid * 8];
        int   bi = redi[tid * 8];
        #pragma unroll
        for (int t = 1; t < 8; t++) {
            float v = redv[tid * 8 + t];
            int  ii = redi[tid * 8 + t];
            if (v < bv || (v == bv && ii < bi)) { bv = v; bi = ii; }
        }
        g_indices[m0 + tid] = bi;
        idxf_out[m0 + tid]  = (float)bi;
    }
}

// ============================================================
// Kernel 3: gather z_q, straight-through output, loss partials,
// counts + dw segment sums. 1 warp per z-row, 8 rows per block.
// ============================================================
__global__ void __launch_bounds__(256)
scatter_kernel(const float* __restrict__ z, const float* __restrict__ emb,
               float* __restrict__ zq_out) {
    const int warp = threadIdx.x >> 5;
    const int lane = threadIdx.x & 31;
    const int row  = blockIdx.x * 8 + warp;

    const int idx = g_indices[row];

    float4 f = *reinterpret_cast<const float4*>(&z[(size_t)row * D_DIM + lane * 4]);
    float4 q = *reinterpret_cast<const float4*>(&emb[(size_t)idx * D_DIM + lane * 4]);

    float dx = q.x - f.x, dy = q.y - f.y, dz = q.z - f.z, dw4 = q.w - f.w;
    float4 st = make_float4(f.x + dx, f.y + dy, f.z + dz, f.w + dw4);
    *reinterpret_cast<float4*>(&zq_out[(size_t)row * D_DIM + lane * 4]) = st;

    float lsum = dx * dx + dy * dy + dz * dz + dw4 * dw4;

    float* dwp = &g_dw[idx * D_DIM + lane * 4];
    atomicAdd(dwp + 0, f.x);
    atomicAdd(dwp + 1, f.y);
    atomicAdd(dwp + 2, f.z);
    atomicAdd(dwp + 3, f.w);

    if (lane == 0) atomicAdd(&g_counts[idx], 1.0f);

    #pragma unroll
    for (int off = 16; off > 0; off >>= 1) lsum += __shfl_xor_sync(0xFFFFFFFFu, lsum, off);
    __shared__ float s_l[8];
    if (lane == 0) s_l[warp] = lsum;
    __syncthreads();
    if (threadIdx.x == 0) {
        float b = 0.0f;
        #pragma unroll
        for (int w = 0; w < 8; w++) b += s_l[w];
        atomicAdd(&g_loss_part[blockIdx.x & 63], b);
    }
}

// ============================================================
// Kernel 4a: scalar finalize — ecs EMA, n-reduce, cluster size, loss.
// ============================================================
__global__ void __launch_bounds__(512)
finalize_a(const float* __restrict__ ecs, float* __restrict__ o_ecs,
           float* __restrict__ o_loss, int N) {
    const int k = threadIdx.x;
    __shared__ float red[K_DIM];

    float necs = ecs[k] * DECAY_F + ONE_M_DECAY * g_counts[k];
    o_ecs[k] = necs;
    red[k] = necs;
    __syncthreads();
    #pragma unroll
    for (int s = 256; s > 0; s >>= 1) {
        if (k < s) red[k] += red[k + s];
        __syncthreads();
    }
    float n = red[0];
    g_cs[k] = (necs + EPS_F) / (n + (float)K_DIM * EPS_F) * n;

    if (k == 0) {
        float L = 0.0f;
        #pragma unroll
        for (int j = 0; j < 64; j++) L += g_loss_part[j];
        *o_loss = COMMIT * L / ((float)N * (float)D_DIM);
    }
}

// ============================================================
// Kernel 4b: wide finalize — ema_w EMA + new embedding (K*D elems).
// ============================================================
__global__ void __launch_bounds__(256)
finalize_b(const float* __restrict__ emaw, float* __restrict__ o_emaw,
           float* __restrict__ o_emb) {
    int i = blockIdx.x * 256 + threadIdx.x;
    float w = emaw[i] * DECAY_F + ONE_M_DECAY * g_dw[i];
    o_emaw[i] = w;
    o_emb[i]  = w / g_cs[i >> 7];
}

// ============================================================
// launch
// ============================================================
extern "C" void kernel_launch(void* const* d_in, const int* in_sizes, int n_in,
                              void* d_out, int out_size) {
    const float* z    = (const float*)d_in[0];   // [N, 128]
    const float* emb  = (const float*)d_in[1];   // [512, 128]
    const float* ecs  = (const float*)d_in[2];   // [512]
    const float* emaw = (const float*)d_in[3];   // [512, 128]

    const int ND = in_sizes[0];
    const int KD = in_sizes[1];
    const int K  = in_sizes[2];
    const int N  = ND / D_DIM;

    float* out    = (float*)d_out;
    float* o_zq   = out;                 // N*D
    float* o_loss = o_zq + ND;           // 1
    float* o_idx  = o_loss + 1;          // N
    float* o_ecs  = o_idx + N;           // K
    float* o_emaw = o_ecs + K;           // K*D
    float* o_emb  = o_emaw + KD;         // K*D

    // dyn smem: zs (128*132) + es (64*132) floats = 99 KB -> 2 CTAs/SM
    const int dyn_smem = (128 * ZSTRIDE + 64 * ESTRIDE) * 4;
    cudaFuncSetAttribute(argmin_kernel,
                         cudaFuncAttributeMaxDynamicSharedMemorySize, dyn_smem);

    init_kernel<<<64, 256>>>(emb);
    argmin_kernel<<<N / 128, 256, dyn_smem>>>(z, emb, o_idx);
    scatter_kernel<<<N / 8, 256>>>(z, emb, o_zq);
    finalize_a<<<1, 512>>>(ecs, o_ecs, o_loss, N);
    finalize_b<<<KD / 256, 256>>>(emaw, o_emaw, o_emb);
}

// round 8
// speedup vs baseline: 2.0853x; 1.3708x over previous
#include <cuda_runtime.h>
#include <cuda_fp16.h>
#include <cuda_bf16.h>
#include <cstdint>

#define D_DIM   128
#define K_DIM   512
#define N_MAX   262144

#define DECAY_F 0.99f
#define ONE_M_DECAY 0.01f
#define EPS_F   1e-5f
#define COMMIT  0.25f

#define ZP 68   // z row stride in half2/uint32 units (68 -> bank-conflict-free frags)
#define EP 68   // e row stride in half2/uint32 units

// -------- device scratch (static: no allocation) --------
__device__ int   g_indices[N_MAX];
__device__ float g_counts[K_DIM];
__device__ float g_dw[K_DIM * D_DIM];
__device__ float g_enorm[K_DIM];
__device__ float g_loss_part[64];
__device__ float g_cs[K_DIM];

// split a float2 into fp16 hi (rounded) and fp16 lo (residual), packed as half2
__device__ __forceinline__ void split_h2(float2 v, uint32_t& hi, uint32_t& lo) {
    half2 h = __float22half2_rn(v);
    float2 f = __half22float2(h);
    half2 l = __float22half2_rn(make_float2(v.x - f.x, v.y - f.y));
    hi = *reinterpret_cast<uint32_t*>(&h);
    lo = *reinterpret_cast<uint32_t*>(&l);
}

// D += A(16x16 f16, row) * B(16x8 f16, col), fp32 accum  [base-PTX, sm_80+]
__device__ __forceinline__ void mma_f16(float* d, const uint32_t* a, const uint32_t* b) {
    asm volatile(
        "mma.sync.aligned.m16n8k16.row.col.f32.f16.f16.f32 "
        "{%0,%1,%2,%3}, {%4,%5,%6,%7}, {%8,%9}, {%0,%1,%2,%3};"
        : "+f"(d[0]), "+f"(d[1]), "+f"(d[2]), "+f"(d[3])
        : "r"(a[0]), "r"(a[1]), "r"(a[2]), "r"(a[3]), "r"(b[0]), "r"(b[1]));
}

// ============================================================
// Kernel 1: zero accumulators + ||e_k||^2
// ============================================================
__global__ void __launch_bounds__(256) init_kernel(const float* __restrict__ emb) {
    int tid = blockIdx.x * blockDim.x + threadIdx.x;
    for (int i = tid; i < K_DIM * D_DIM; i += 16384) g_dw[i] = 0.0f;
    if (tid < K_DIM) g_counts[tid] = 0.0f;
    if (tid < 64)    g_loss_part[tid] = 0.0f;

    int w = tid >> 5, lane = tid & 31;
    float4 v = *reinterpret_cast<const float4*>(&emb[w * D_DIM + lane * 4]);
    float s = v.x * v.x + v.y * v.y + v.z * v.z + v.w * v.w;
    #pragma unroll
    for (int off = 16; off > 0; off >>= 1) s += __shfl_xor_sync(0xFFFFFFFFu, s, off);
    if (lane == 0) g_enorm[w] = s;
}

// ============================================================
// Kernel 2: 3-term fp16 mma.sync (m16n8k16) GEMM + fused argmin.
// z/e pre-split into packed half2 hi/lo smem tiles (split hoisted out of
// the mainloop). 104.5KB smem -> 2 CTAs/SM.
// CTA: 128 z-rows x 512 codes. 256 threads = 8 warps as 4(m) x 2(n).
// score[n][k] = ||e_k||^2 - 2*dot(z_n, e_k); per-thread running argmin.
// ============================================================
__global__ void __launch_bounds__(256, 2)
argmin_kernel(const float* __restrict__ z, const float* __restrict__ emb,
              float* __restrict__ idxf_out) {
    extern __shared__ uint32_t sm[];
    uint32_t* zh = sm;                    // [128][68] half2 (hi)
    uint32_t* zl = zh + 128 * ZP;         // [128][68] half2 (lo)
    uint32_t* eh = zl + 128 * ZP;         // [64][68]  half2 (hi)
    uint32_t* el = eh + 64 * EP;          // [64][68]  half2 (lo)
    __shared__ float en[K_DIM];

    const int tid  = threadIdx.x;
    const int warp = tid >> 5;
    const int lane = tid & 31;
    const int g    = lane >> 2;      // groupID (0..7)
    const int tig  = lane & 3;       // threadID_in_group (0..3)
    const int wm   = warp >> 1;      // 0..3  (rows wm*32 .. +32)
    const int wn   = warp & 1;       // 0..1  (cols wn*32 within chunk)
    const int m0   = blockIdx.x * 128;

    #pragma unroll
    for (int i = 0; i < 2; i++) en[tid + i * 256] = g_enorm[tid + i * 256];

    // ---- stage z tile: split to fp16 hi/lo half2 (coalesced float2 loads) ----
    for (int idx = tid; idx < 128 * 64; idx += 256) {
        int r = idx >> 6, c2 = idx & 63;
        float2 v = *reinterpret_cast<const float2*>(z + (size_t)(m0 + r) * D_DIM + c2 * 2);
        uint32_t hi, lo;
        split_h2(v, hi, lo);
        zh[r * ZP + c2] = hi;
        zl[r * ZP + c2] = lo;
    }

    // best[ri]: ri = (mf<<1) | half, covering rows wm*32 + mf*16 + half*8 + g
    float best[4];
    int   besti[4];
    #pragma unroll
    for (int i = 0; i < 4; i++) { best[i] = 3.4e38f; besti[i] = 0; }

    const int rbase = wm * 32 + g;

    for (int ch = 0; ch < 8; ch++) {
        __syncthreads();   // previous chunk's MMAs done reading eh/el
        for (int idx = tid; idx < 64 * 64; idx += 256) {
            int n = idx >> 6, c2 = idx & 63;
            float2 v = *reinterpret_cast<const float2*>(
                emb + (size_t)(ch * 64 + n) * D_DIM + c2 * 2);
            uint32_t hi, lo;
            split_h2(v, hi, lo);
            eh[n * EP + c2] = hi;
            el[n * EP + c2] = lo;
        }
        __syncthreads();

        float acc[2][4][4];
        #pragma unroll
        for (int mf = 0; mf < 2; mf++)
            #pragma unroll
            for (int nf = 0; nf < 4; nf++)
                #pragma unroll
                for (int c = 0; c < 4; c++) acc[mf][nf][c] = 0.0f;

        #pragma unroll
        for (int ks = 0; ks < 8; ks++) {        // 8 k16-steps cover D=128
            const int k2 = ks * 8;

            // A fragments (m16k16): a0=(g, k2+2tig) a1=(g+8,..) a2=(g, k2+8+2tig) a3=(g+8,..)
            uint32_t ah[2][4], al[2][4];
            #pragma unroll
            for (int mf = 0; mf < 2; mf++) {
                const int r = (rbase + mf * 16) * ZP + k2 + tig;
                ah[mf][0] = zh[r];
                ah[mf][1] = zh[r + 8 * ZP];
                ah[mf][2] = zh[r + 4];
                ah[mf][3] = zh[r + 8 * ZP + 4];
                al[mf][0] = zl[r];
                al[mf][1] = zl[r + 8 * ZP];
                al[mf][2] = zl[r + 4];
                al[mf][3] = zl[r + 8 * ZP + 4];
            }
            // B fragments (k16n8, col): b0 = k2+2tig row-pair, b1 = k2+8+2tig
            uint32_t bh[4][2], bl[4][2];
            #pragma unroll
            for (int nf = 0; nf < 4; nf++) {
                const int nb = (wn * 32 + nf * 8 + g) * EP + k2 + tig;
                bh[nf][0] = eh[nb];
                bh[nf][1] = eh[nb + 4];
                bl[nf][0] = el[nb];
                bl[nf][1] = el[nb + 4];
            }

            // term 1: hi*hi  (8 independent accumulators between dependent reuses)
            #pragma unroll
            for (int mf = 0; mf < 2; mf++)
                #pragma unroll
                for (int nf = 0; nf < 4; nf++) mma_f16(acc[mf][nf], ah[mf], bh[nf]);
            // term 2: hi*lo
            #pragma unroll
            for (int mf = 0; mf < 2; mf++)
                #pragma unroll
                for (int nf = 0; nf < 4; nf++) mma_f16(acc[mf][nf], ah[mf], bl[nf]);
            // term 3: lo*hi
            #pragma unroll
            for (int mf = 0; mf < 2; mf++)
                #pragma unroll
                for (int nf = 0; nf < 4; nf++) mma_f16(acc[mf][nf], al[mf], bh[nf]);
        }

        // epilogue. Accumulator c holds (row = base + (c>>1)*8, col = colb + (c&1)).
        // Column traversal ascending -> lowest-index tie-break preserved.
        #pragma unroll
        for (int mf = 0; mf < 2; mf++) {
            #pragma unroll
            for (int nf = 0; nf < 4; nf++) {
                const int colb = ch * 64 + wn * 32 + nf * 8 + 2 * tig;
                #pragma unroll
                for (int c = 0; c < 4; c++) {
                    const int col = colb + (c & 1);
                    const int ri  = mf * 2 + (c >> 1);
                    float s = en[col] - 2.0f * acc[mf][nf][c];
                    if (s < best[ri]) { best[ri] = s; besti[ri] = col; }
                }
            }
        }
    }

    // ---- final per-row reduce (8 contributors/row), reuse eh region ----
    __syncthreads();
    float* redv = reinterpret_cast<float*>(eh);          // [128][8]
    int*   redi = reinterpret_cast<int*>(eh) + 128 * 8;  // [128][8]
    const int slot = tig * 2 + wn;
    #pragma unroll
    for (int ri = 0; ri < 4; ri++) {
        const int r = wm * 32 + (ri >> 1) * 16 + (ri & 1) * 8 + g;
        redv[r * 8 + slot] = best[ri];
        redi[r * 8 + slot] = besti[ri];
    }
    __syncthreads();
    if (tid < 128) {
        float bv = redv[tid * 8];
        int   bi = redi[tid * 8];
        #pragma unroll
        for (int t = 1; t < 8; t++) {
            float v = redv[tid * 8 + t];
            int  ii = redi[tid * 8 + t];
            if (v < bv || (v == bv && ii < bi)) { bv = v; bi = ii; }
        }
        g_indices[m0 + tid] = bi;
        idxf_out[m0 + tid]  = (float)bi;
    }
}

// ============================================================
// Kernel 3: gather z_q, straight-through output, loss partials,
// counts + dw segment sums. 1 warp per z-row, 8 rows per block.
// ============================================================
__global__ void __launch_bounds__(256)
scatter_kernel(const float* __restrict__ z, const float* __restrict__ emb,
               float* __restrict__ zq_out) {
    const int warp = threadIdx.x >> 5;
    const int lane = threadIdx.x & 31;
    const int row  = blockIdx.x * 8 + warp;

    const int idx = g_indices[row];

    float4 f = *reinterpret_cast<const float4*>(&z[(size_t)row * D_DIM + lane * 4]);
    float4 q = *reinterpret_cast<const float4*>(&emb[(size_t)idx * D_DIM + lane * 4]);

    float dx = q.x - f.x, dy = q.y - f.y, dz = q.z - f.z, dw4 = q.w - f.w;
    float4 st = make_float4(f.x + dx, f.y + dy, f.z + dz, f.w + dw4);
    *reinterpret_cast<float4*>(&zq_out[(size_t)row * D_DIM + lane * 4]) = st;

    float lsum = dx * dx + dy * dy + dz * dz + dw4 * dw4;

    float* dwp = &g_dw[idx * D_DIM + lane * 4];
    atomicAdd(dwp + 0, f.x);
    atomicAdd(dwp + 1, f.y);
    atomicAdd(dwp + 2, f.z);
    atomicAdd(dwp + 3, f.w);

    if (lane == 0) atomicAdd(&g_counts[idx], 1.0f);

    #pragma unroll
    for (int off = 16; off > 0; off >>= 1) lsum += __shfl_xor_sync(0xFFFFFFFFu, lsum, off);
    __shared__ float s_l[8];
    if (lane == 0) s_l[warp] = lsum;
    __syncthreads();
    if (threadIdx.x == 0) {
        float b = 0.0f;
        #pragma unroll
        for (int w = 0; w < 8; w++) b += s_l[w];
        atomicAdd(&g_loss_part[blockIdx.x & 63], b);
    }
}

// ============================================================
// Kernel 4a: scalar finalize — ecs EMA, n-reduce, cluster size, loss.
// ============================================================
__global__ void __launch_bounds__(512)
finalize_a(const float* __restrict__ ecs, float* __restrict__ o_ecs,
           float* __restrict__ o_loss, int N) {
    const int k = threadIdx.x;
    __shared__ float red[K_DIM];

    float necs = ecs[k] * DECAY_F + ONE_M_DECAY * g_counts[k];
    o_ecs[k] = necs;
    red[k] = necs;
    __syncthreads();
    #pragma unroll
    for (int s = 256; s > 0; s >>= 1) {
        if (k < s) red[k] += red[k + s];
        __syncthreads();
    }
    float n = red[0];
    g_cs[k] = (necs + EPS_F) / (n + (float)K_DIM * EPS_F) * n;

    if (k == 0) {
        float L = 0.0f;
        #pragma unroll
        for (int j = 0; j < 64; j++) L += g_loss_part[j];
        *o_loss = COMMIT * L / ((float)N * (float)D_DIM);
    }
}

// ============================================================
// Kernel 4b: wide finalize — ema_w EMA + new embedding (K*D elems).
// ============================================================
__global__ void __launch_bounds__(256)
finalize_b(const float* __restrict__ emaw, float* __restrict__ o_emaw,
           float* __restrict__ o_emb) {
    int i = blockIdx.x * 256 + threadIdx.x;
    float w = emaw[i] * DECAY_F + ONE_M_DECAY * g_dw[i];
    o_emaw[i] = w;
    o_emb[i]  = w / g_cs[i >> 7];
}

// ============================================================
// launch
// ============================================================
extern "C" void kernel_launch(void* const* d_in, const int* in_sizes, int n_in,
                              void* d_out, int out_size) {
    const float* z    = (const float*)d_in[0];   // [N, 128]
    const float* emb  = (const float*)d_in[1];   // [512, 128]
    const float* ecs  = (const float*)d_in[2];   // [512]
    const float* emaw = (const float*)d_in[3];   // [512, 128]

    const int ND = in_sizes[0];
    const int KD = in_sizes[1];
    const int K  = in_sizes[2];
    const int N  = ND / D_DIM;

    float* out    = (float*)d_out;
    float* o_zq   = out;                 // N*D
    float* o_loss = o_zq + ND;           // 1
    float* o_idx  = o_loss + 1;          // N
    float* o_ecs  = o_idx + N;           // K
    float* o_emaw = o_ecs + K;           // K*D
    float* o_emb  = o_emaw + KD;         // K*D

    // dyn smem: (zh+zl)=2*128*68 + (eh+el)=2*64*68 uint32 = 104448 B -> 2 CTAs/SM
    const int dyn_smem = (2 * 128 * ZP + 2 * 64 * EP) * 4;
    cudaFuncSetAttribute(argmin_kernel,
                         cudaFuncAttributeMaxDynamicSharedMemorySize, dyn_smem);

    init_kernel<<<64, 256>>>(emb);
    argmin_kernel<<<N / 128, 256, dyn_smem>>>(z, emb, o_idx);
    scatter_kernel<<<N / 8, 256>>>(z, emb, o_zq);
    finalize_a<<<1, 512>>>(ecs, o_ecs, o_loss, N);
    finalize_b<<<KD / 256, 256>>>(emaw, o_emaw, o_emb);
}

// round 9
// speedup vs baseline: 2.9976x; 1.4375x over previous
#include <cuda_runtime.h>
#include <cuda_fp16.h>
#include <cuda_bf16.h>
#include <cstdint>

#define D_DIM   128
#define K_DIM   512
#define N_MAX   262144

#define DECAY_F 0.99f
#define ONE_M_DECAY 0.01f
#define EPS_F   1e-5f
#define COMMIT  0.25f

#define ZP 68   // z row stride in half2/uint32 units (bank-conflict-free frags)
#define EP 68   // e row stride in half2/uint32 units

// -------- device scratch (static: no allocation) --------
__device__ int   g_indices[N_MAX];
__device__ float g_counts[K_DIM];
__device__ float g_dw[K_DIM * D_DIM];
__device__ float g_enorm[K_DIM];
__device__ float g_loss_part[64];
__device__ float g_cs[K_DIM];

// split a float2 into fp16 hi (rounded) and fp16 lo (residual), packed as half2
__device__ __forceinline__ void split_h2(float2 v, uint32_t& hi, uint32_t& lo) {
    half2 h = __float22half2_rn(v);
    float2 f = __half22float2(h);
    half2 l = __float22half2_rn(make_float2(v.x - f.x, v.y - f.y));
    hi = *reinterpret_cast<uint32_t*>(&h);
    lo = *reinterpret_cast<uint32_t*>(&l);
}

// D += A(16x16 f16, row) * B(16x8 f16, col), fp32 accum  [base-PTX, sm_80+]
__device__ __forceinline__ void mma_f16(float* d, const uint32_t* a, const uint32_t* b) {
    asm volatile(
        "mma.sync.aligned.m16n8k16.row.col.f32.f16.f16.f32 "
        "{%0,%1,%2,%3}, {%4,%5,%6,%7}, {%8,%9}, {%0,%1,%2,%3};"
        : "+f"(d[0]), "+f"(d[1]), "+f"(d[2]), "+f"(d[3])
        : "r"(a[0]), "r"(a[1]), "r"(a[2]), "r"(a[3]), "r"(b[0]), "r"(b[1]));
}

// ============================================================
// Kernel 1: zero accumulators + ||e_k||^2
// ============================================================
__global__ void __launch_bounds__(256) init_kernel(const float* __restrict__ emb) {
    int tid = blockIdx.x * blockDim.x + threadIdx.x;
    for (int i = tid; i < K_DIM * D_DIM; i += 16384) g_dw[i] = 0.0f;
    if (tid < K_DIM) g_counts[tid] = 0.0f;
    if (tid < 64)    g_loss_part[tid] = 0.0f;

    int w = tid >> 5, lane = tid & 31;
    float4 v = *reinterpret_cast<const float4*>(&emb[w * D_DIM + lane * 4]);
    float s = v.x * v.x + v.y * v.y + v.z * v.z + v.w * v.w;
    #pragma unroll
    for (int off = 16; off > 0; off >>= 1) s += __shfl_xor_sync(0xFFFFFFFFu, s, off);
    if (lane == 0) g_enorm[w] = s;
}

// ============================================================
// Kernel 2 (FUSED): 3-term fp16 mma.sync GEMM + argmin + scatter tail.
// Phase A: scores + per-thread argmin (MMA-issue-bound).
// Phase B: per-row reduce -> indices.
// Phase C: scatter (zq write, loss, counts, dw atomics) for this CTA's
//          128 rows; overlaps other CTAs' Phase A at SM/chip level.
// ============================================================
__global__ void __launch_bounds__(256, 2)
argmin_kernel(const float* __restrict__ z, const float* __restrict__ emb,
              float* __restrict__ idxf_out, float* __restrict__ zq_out) {
    extern __shared__ uint32_t sm[];
    uint32_t* zh = sm;                    // [128][68] half2 (hi)
    uint32_t* zl = zh + 128 * ZP;         // [128][68] half2 (lo)
    uint32_t* eh = zl + 128 * ZP;         // [64][68]  half2 (hi)
    uint32_t* el = eh + 64 * EP;          // [64][68]  half2 (lo)
    __shared__ float en[K_DIM];
    __shared__ int   s_idx[128];

    const int tid  = threadIdx.x;
    const int warp = tid >> 5;
    const int lane = tid & 31;
    const int g    = lane >> 2;      // groupID (0..7)
    const int tig  = lane & 3;       // threadID_in_group (0..3)
    const int wm   = warp >> 1;      // 0..3  (rows wm*32 .. +32)
    const int wn   = warp & 1;       // 0..1  (cols wn*32 within chunk)
    const int m0   = blockIdx.x * 128;

    #pragma unroll
    for (int i = 0; i < 2; i++) en[tid + i * 256] = g_enorm[tid + i * 256];

    // ---- stage z tile: split to fp16 hi/lo half2 (coalesced float2 loads) ----
    for (int idx = tid; idx < 128 * 64; idx += 256) {
        int r = idx >> 6, c2 = idx & 63;
        float2 v = *reinterpret_cast<const float2*>(z + (size_t)(m0 + r) * D_DIM + c2 * 2);
        uint32_t hi, lo;
        split_h2(v, hi, lo);
        zh[r * ZP + c2] = hi;
        zl[r * ZP + c2] = lo;
    }

    // best[ri]: ri = (mf<<1) | half, covering rows wm*32 + mf*16 + half*8 + g
    float best[4];
    int   besti[4];
    #pragma unroll
    for (int i = 0; i < 4; i++) { best[i] = 3.4e38f; besti[i] = 0; }

    const int rbase = wm * 32 + g;

    for (int ch = 0; ch < 8; ch++) {
        // prefetch e-chunk into registers BEFORE the sync: LDG latency hides
        // under the other warps draining chunk ch-1 MMAs.
        float2 pre[16];
        {
            const float* ebase = emb + (size_t)(ch * 64) * D_DIM;
            #pragma unroll
            for (int i = 0; i < 16; i++) {
                int idx = tid + i * 256;
                int n = idx >> 6, c2 = idx & 63;
                pre[i] = *reinterpret_cast<const float2*>(ebase + n * D_DIM + c2 * 2);
            }
        }
        __syncthreads();   // previous chunk's MMAs done reading eh/el
        #pragma unroll
        for (int i = 0; i < 16; i++) {
            int idx = tid + i * 256;
            int n = idx >> 6, c2 = idx & 63;
            uint32_t hi, lo;
            split_h2(pre[i], hi, lo);
            eh[n * EP + c2] = hi;
            el[n * EP + c2] = lo;
        }
        __syncthreads();

        float acc[2][4][4];
        #pragma unroll
        for (int mf = 0; mf < 2; mf++)
            #pragma unroll
            for (int nf = 0; nf < 4; nf++)
                #pragma unroll
                for (int c = 0; c < 4; c++) acc[mf][nf][c] = 0.0f;

        #pragma unroll
        for (int ks = 0; ks < 8; ks++) {        // 8 k16-steps cover D=128
            const int k2 = ks * 8;

            // A fragments (m16k16)
            uint32_t ah[2][4], al[2][4];
            #pragma unroll
            for (int mf = 0; mf < 2; mf++) {
                const int r = (rbase + mf * 16) * ZP + k2 + tig;
                ah[mf][0] = zh[r];
                ah[mf][1] = zh[r + 8 * ZP];
                ah[mf][2] = zh[r + 4];
                ah[mf][3] = zh[r + 8 * ZP + 4];
                al[mf][0] = zl[r];
                al[mf][1] = zl[r + 8 * ZP];
                al[mf][2] = zl[r + 4];
                al[mf][3] = zl[r + 8 * ZP + 4];
            }
            // B fragments (k16n8, col-major)
            uint32_t bh[4][2], bl[4][2];
            #pragma unroll
            for (int nf = 0; nf < 4; nf++) {
                const int nb = (wn * 32 + nf * 8 + g) * EP + k2 + tig;
                bh[nf][0] = eh[nb];
                bh[nf][1] = eh[nb + 4];
                bl[nf][0] = el[nb];
                bl[nf][1] = el[nb + 4];
            }

            // term 1: hi*hi
            #pragma unroll
            for (int mf = 0; mf < 2; mf++)
                #pragma unroll
                for (int nf = 0; nf < 4; nf++) mma_f16(acc[mf][nf], ah[mf], bh[nf]);
            // term 2: hi*lo
            #pragma unroll
            for (int mf = 0; mf < 2; mf++)
                #pragma unroll
                for (int nf = 0; nf < 4; nf++) mma_f16(acc[mf][nf], ah[mf], bl[nf]);
            // term 3: lo*hi
            #pragma unroll
            for (int mf = 0; mf < 2; mf++)
                #pragma unroll
                for (int nf = 0; nf < 4; nf++) mma_f16(acc[mf][nf], al[mf], bh[nf]);
        }

        // epilogue. Accumulator c holds (row = base + (c>>1)*8, col = colb + (c&1)).
        // Column traversal ascending -> lowest-index tie-break preserved.
        #pragma unroll
        for (int mf = 0; mf < 2; mf++) {
            #pragma unroll
            for (int nf = 0; nf < 4; nf++) {
                const int colb = ch * 64 + wn * 32 + nf * 8 + 2 * tig;
                #pragma unroll
                for (int c = 0; c < 4; c++) {
                    const int col = colb + (c & 1);
                    const int ri  = mf * 2 + (c >> 1);
                    float s = en[col] - 2.0f * acc[mf][nf][c];
                    if (s < best[ri]) { best[ri] = s; besti[ri] = col; }
                }
            }
        }
    }

    // ---- Phase B: per-row reduce (8 contributors/row), reuse eh region ----
    __syncthreads();
    float* redv = reinterpret_cast<float*>(eh);          // [128][8]
    int*   redi = reinterpret_cast<int*>(eh) + 128 * 8;  // [128][8]
    const int slot = tig * 2 + wn;
    #pragma unroll
    for (int ri = 0; ri < 4; ri++) {
        const int r = wm * 32 + (ri >> 1) * 16 + (ri & 1) * 8 + g;
        redv[r * 8 + slot] = best[ri];
        redi[r * 8 + slot] = besti[ri];
    }
    __syncthreads();
    if (tid < 128) {
        float bv = redv[tid * 8];
        int   bi = redi[tid * 8];
        #pragma unroll
        for (int t = 1; t < 8; t++) {
            float v = redv[tid * 8 + t];
            int  ii = redi[tid * 8 + t];
            if (v < bv || (v == bv && ii < bi)) { bv = v; bi = ii; }
        }
        g_indices[m0 + tid] = bi;
        idxf_out[m0 + tid]  = (float)bi;
        s_idx[tid]          = bi;
    }
    __syncthreads();

    // ---- Phase C: scatter this CTA's 128 rows (warp per row, 16 rows/warp) ----
    float lacc = 0.0f;
    #pragma unroll 4
    for (int it = 0; it < 16; it++) {
        const int r   = warp * 16 + it;
        const int row = m0 + r;
        const int idx = s_idx[r];

        float4 f = *reinterpret_cast<const float4*>(&z[(size_t)row * D_DIM + lane * 4]);
        float4 q = *reinterpret_cast<const float4*>(&emb[(size_t)idx * D_DIM + lane * 4]);

        float dx = q.x - f.x, dy = q.y - f.y, dz = q.z - f.z, dw4 = q.w - f.w;
        float4 st = make_float4(f.x + dx, f.y + dy, f.z + dz, f.w + dw4);
        *reinterpret_cast<float4*>(&zq_out[(size_t)row * D_DIM + lane * 4]) = st;

        lacc += dx * dx + dy * dy + dz * dz + dw4 * dw4;

        float* dwp = &g_dw[idx * D_DIM + lane * 4];
        atomicAdd(dwp + 0, f.x);
        atomicAdd(dwp + 1, f.y);
        atomicAdd(dwp + 2, f.z);
        atomicAdd(dwp + 3, f.w);

        if (lane == 0) atomicAdd(&g_counts[idx], 1.0f);
    }
    // loss reduce: warp -> block partial
    #pragma unroll
    for (int off = 16; off > 0; off >>= 1) lacc += __shfl_xor_sync(0xFFFFFFFFu, lacc, off);
    __shared__ float s_l[8];
    if (lane == 0) s_l[warp] = lacc;
    __syncthreads();
    if (tid == 0) {
        float b = 0.0f;
        #pragma unroll
        for (int w = 0; w < 8; w++) b += s_l[w];
        atomicAdd(&g_loss_part[blockIdx.x & 63], b);
    }
}

// ============================================================
// Kernel 3a: scalar finalize — ecs EMA, n-reduce, cluster size, loss.
// ============================================================
__global__ void __launch_bounds__(512)
finalize_a(const float* __restrict__ ecs, float* __restrict__ o_ecs,
           float* __restrict__ o_loss, int N) {
    const int k = threadIdx.x;
    __shared__ float red[K_DIM];

    float necs = ecs[k] * DECAY_F + ONE_M_DECAY * g_counts[k];
    o_ecs[k] = necs;
    red[k] = necs;
    __syncthreads();
    #pragma unroll
    for (int s = 256; s > 0; s >>= 1) {
        if (k < s) red[k] += red[k + s];
        __syncthreads();
    }
    float n = red[0];
    g_cs[k] = (necs + EPS_F) / (n + (float)K_DIM * EPS_F) * n;

    if (k == 0) {
        float L = 0.0f;
        #pragma unroll
        for (int j = 0; j < 64; j++) L += g_loss_part[j];
        *o_loss = COMMIT * L / ((float)N * (float)D_DIM);
    }
}

// ============================================================
// Kernel 3b: wide finalize — ema_w EMA + new embedding (K*D elems).
// ============================================================
__global__ void __launch_bounds__(256)
finalize_b(const float* __restrict__ emaw, float* __restrict__ o_emaw,
           float* __restrict__ o_emb) {
    int i = blockIdx.x * 256 + threadIdx.x;
    float w = emaw[i] * DECAY_F + ONE_M_DECAY * g_dw[i];
    o_emaw[i] = w;
    o_emb[i]  = w / g_cs[i >> 7];
}

// ============================================================
// launch
// ============================================================
extern "C" void kernel_launch(void* const* d_in, const int* in_sizes, int n_in,
                              void* d_out, int out_size) {
    const float* z    = (const float*)d_in[0];   // [N, 128]
    const float* emb  = (const float*)d_in[1];   // [512, 128]
    const float* ecs  = (const float*)d_in[2];   // [512]
    const float* emaw = (const float*)d_in[3];   // [512, 128]

    const int ND = in_sizes[0];
    const int KD = in_sizes[1];
    const int K  = in_sizes[2];
    const int N  = ND / D_DIM;

    float* out    = (float*)d_out;
    float* o_zq   = out;                 // N*D
    float* o_loss = o_zq + ND;           // 1
    float* o_idx  = o_loss + 1;          // N
    float* o_ecs  = o_idx + N;           // K
    float* o_emaw = o_ecs + K;           // K*D
    float* o_emb  = o_emaw + KD;         // K*D

    // dyn smem: (zh+zl)=2*128*68 + (eh+el)=2*64*68 uint32 = 104448 B -> 2 CTAs/SM
    const int dyn_smem = (2 * 128 * ZP + 2 * 64 * EP) * 4;
    cudaFuncSetAttribute(argmin_kernel,
                         cudaFuncAttributeMaxDynamicSharedMemorySize, dyn_smem);

    init_kernel<<<64, 256>>>(emb);
    argmin_kernel<<<N / 128, 256, dyn_smem>>>(z, emb, o_idx, o_zq);
    finalize_a<<<1, 512>>>(ecs, o_ecs, o_loss, N);
    finalize_b<<<KD / 256, 256>>>(emaw, o_emaw, o_emb);
}